// round 4
// baseline (speedup 1.0000x reference)
#include <cuda_runtime.h>
#include <cuda_bf16.h>
#include <cstdint>

#define NB   32
#define LA   512
#define LB   512
#define DIM  768
#define OUTC 3072

// ---------------- scratch (__device__ globals; no allocation allowed) -------
__device__ __align__(1024) __nv_bfloat16 g_ah [(size_t)NB*LA*DIM], g_al [(size_t)NB*LA*DIM];
__device__ __align__(1024) __nv_bfloat16 g_bh [(size_t)NB*LB*DIM], g_bl [(size_t)NB*LB*DIM];
__device__ __align__(1024) __nv_bfloat16 g_aTh[(size_t)NB*DIM*LA], g_aTl[(size_t)NB*DIM*LA];
__device__ __align__(1024) __nv_bfloat16 g_bTh[(size_t)NB*DIM*LB], g_bTl[(size_t)NB*DIM*LB];
__device__ __align__(1024) __nv_bfloat16 g_ph [(size_t)NB*LA*LB],  g_pl [(size_t)NB*LA*LB];
__device__ __align__(1024) __nv_bfloat16 g_pbTh[(size_t)NB*LB*LA], g_pbTl[(size_t)NB*LB*LA];
__device__ __align__(1024) float g_e[(size_t)NB*LA*LB];
__device__ float g_cmax[NB*LB], g_cinv[NB*LB];

// ---------------- low-level helpers (portable PTX only) ---------------------
__device__ __forceinline__ uint32_t smem_to_u32(const void* p) {
    uint32_t a;
    asm("{ .reg .u64 t; cvta.to.shared.u64 t, %1; cvt.u32.u64 %0, t; }" : "=r"(a) : "l"(p));
    return a;
}
__device__ __forceinline__ void cp16(uint32_t dst, const void* src) {
    asm volatile("cp.async.cg.shared.global [%0], [%1], 16;" :: "r"(dst), "l"(src));
}
__device__ __forceinline__ void cp_commit() { asm volatile("cp.async.commit_group;"); }
__device__ __forceinline__ void cp_wait1()  { asm volatile("cp.async.wait_group 1;"); }

__device__ __forceinline__ void ldsm4(uint32_t* r, uint32_t addr) {
    asm volatile("ldmatrix.sync.aligned.m8n8.x4.shared.b16 {%0,%1,%2,%3}, [%4];"
                 : "=r"(r[0]), "=r"(r[1]), "=r"(r[2]), "=r"(r[3]) : "r"(addr));
}
__device__ __forceinline__ void mma_bf16(float* c, const uint32_t* a, const uint32_t* b) {
    asm volatile("mma.sync.aligned.m16n8k16.row.col.f32.bf16.bf16.f32 "
                 "{%0,%1,%2,%3}, {%4,%5,%6,%7}, {%8,%9}, {%0,%1,%2,%3};"
                 : "+f"(c[0]), "+f"(c[1]), "+f"(c[2]), "+f"(c[3])
                 : "r"(a[0]), "r"(a[1]), "r"(a[2]), "r"(a[3]), "r"(b[0]), "r"(b[1]));
}

// ---------------- split-bf16 HMMA GEMM ---------------------------------------
// C[m,n] = sum_k (Ah+Al)(m,k)*(Bh+Bl)(n,k)  (drop Al*Bl). A,B K-major bf16.
// CTA tile 128x128, BK=32, 8 warps (2 M x 4 N), warp tile 64x32.
// MMA issue order is PASS-MAJOR (hh all 16, then hl, then lh) so writes to the
// same accumulator are 15 independent MMAs apart -> no RAW stall on HMMA.
#define TILE_BYTES 8192            // 2*128*32
#define STAGE_BYTES 32768          // 4 tiles
#define SMEM_DYN (2*STAGE_BYTES + 1024)

template<int MODE>   // 0: plain fp32 store; 1: ESIM epilogue into Out[M,3072]
__global__ __launch_bounds__(256)
void gemm_hmma(const __nv_bfloat16* __restrict__ Ah, const __nv_bfloat16* __restrict__ Al,
               const __nv_bfloat16* __restrict__ Bh, const __nv_bfloat16* __restrict__ Bl,
               const float* __restrict__ Obase, float* __restrict__ Out,
               int M, int N, int K)
{
    extern __shared__ char smraw[];
    uint32_t sm0 = smem_to_u32(smraw);
    uint32_t smb = (sm0 + 1023u) & ~1023u;

    const int tid = threadIdx.x;
    const int lid = tid & 31, wid = tid >> 5;
    const int wm = wid >> 2, wn = wid & 3;            // 2 x 4 warp grid
    const int z = blockIdx.z, m0 = blockIdx.y * 128, n0 = blockIdx.x * 128;

    const __nv_bfloat16* srcs[4] = {
        Ah + ((size_t)z * M + m0) * K, Al + ((size_t)z * M + m0) * K,
        Bh + ((size_t)z * N + n0) * K, Bl + ((size_t)z * N + n0) * K };

    // precompute ldmatrix lane offsets
    const int ar  = (lid & 7) | (((lid >> 3) & 1) << 3);   // 0..15 row-in-tile16
    const int akh = lid >> 4;
    uint32_t aoff[4];
    #pragma unroll
    for (int i = 0; i < 4; i++) {
        int m = wm * 64 + i * 16 + ar;
        aoff[i] = m * 32 + ((akh ^ ((m >> 2) & 1)) << 4);
    }
    const int br  = (lid & 7) | ((lid >> 4) << 3);
    const int bkh = (lid >> 3) & 1;
    uint32_t boff[2];
    #pragma unroll
    for (int j2 = 0; j2 < 2; j2++) {
        int n = wn * 32 + j2 * 16 + br;
        boff[j2] = n * 32 + ((bkh ^ ((n >> 2) & 1)) << 4);
    }

    float acc[4][4][4];
    #pragma unroll
    for (int i = 0; i < 4; i++)
        #pragma unroll
        for (int j = 0; j < 4; j++)
            #pragma unroll
            for (int r = 0; r < 4; r++) acc[i][j][r] = 0.f;

    const int nk = K >> 5;   // K / 32

    auto issue_stage = [&](int s, int kt) {
        uint32_t sb = smb + s * STAGE_BYTES;
        #pragma unroll
        for (int tl = 0; tl < 4; tl++) {
            const __nv_bfloat16* src = srcs[tl];
            uint32_t tb = sb + tl * TILE_BYTES;
            #pragma unroll
            for (int it = 0; it < 2; it++) {
                int idx = tid + it * 256;          // 0..511
                int m  = idx >> 2;
                int ks = (idx >> 1) & 1;
                int kh = idx & 1;
                uint32_t d = tb + ks * 4096 + m * 32 + ((kh ^ ((m >> 2) & 1)) << 4);
                cp16(d, src + (size_t)m * K + kt * 32 + ks * 16 + kh * 8);
            }
        }
    };

    issue_stage(0, 0);
    cp_commit();

    for (int kt = 0; kt < nk; kt++) {
        if (kt + 1 < nk) issue_stage((kt + 1) & 1, kt + 1);
        cp_commit();
        cp_wait1();
        __syncthreads();

        uint32_t st = smb + (kt & 1) * STAGE_BYTES;
        #pragma unroll
        for (int ks = 0; ks < 2; ks++) {
            uint32_t a_h[4][4], a_l[4][4], b_h[4][2], b_l[4][2];
            #pragma unroll
            for (int i = 0; i < 4; i++) {
                ldsm4(a_h[i], st + 0 * TILE_BYTES + ks * 4096 + aoff[i]);
                ldsm4(a_l[i], st + 1 * TILE_BYTES + ks * 4096 + aoff[i]);
            }
            #pragma unroll
            for (int j2 = 0; j2 < 2; j2++) {
                uint32_t rh[4], rl[4];
                ldsm4(rh, st + 2 * TILE_BYTES + ks * 4096 + boff[j2]);
                ldsm4(rl, st + 3 * TILE_BYTES + ks * 4096 + boff[j2]);
                b_h[j2*2+0][0] = rh[0]; b_h[j2*2+0][1] = rh[1];
                b_h[j2*2+1][0] = rh[2]; b_h[j2*2+1][1] = rh[3];
                b_l[j2*2+0][0] = rl[0]; b_l[j2*2+0][1] = rl[1];
                b_l[j2*2+1][0] = rl[2]; b_l[j2*2+1][1] = rl[3];
            }
            // PASS-MAJOR: all 16 hh MMAs, then 16 hl, then 16 lh.
            // Same-accumulator reuses are 16 issues apart -> RAW fully hidden.
            #pragma unroll
            for (int i = 0; i < 4; i++)
                #pragma unroll
                for (int j = 0; j < 4; j++)
                    mma_bf16(acc[i][j], a_h[i], b_h[j]);
            #pragma unroll
            for (int i = 0; i < 4; i++)
                #pragma unroll
                for (int j = 0; j < 4; j++)
                    mma_bf16(acc[i][j], a_h[i], b_l[j]);
            #pragma unroll
            for (int i = 0; i < 4; i++)
                #pragma unroll
                for (int j = 0; j < 4; j++)
                    mma_bf16(acc[i][j], a_l[i], b_h[j]);
        }
        __syncthreads();
    }

    // ---- epilogue: fragments -> global (32B sector stores) ----
    const int g = lid >> 2, t = lid & 3;
    #pragma unroll
    for (int i = 0; i < 4; i++) {
        #pragma unroll
        for (int j = 0; j < 4; j++) {
            int n = n0 + wn * 32 + j * 8 + t * 2;
            #pragma unroll
            for (int half = 0; half < 2; half++) {
                int m = m0 + wm * 64 + i * 16 + g + half * 8;
                float2 v = make_float2(acc[i][j][half*2+0], acc[i][j][half*2+1]);
                if (MODE == 0) {
                    *(float2*)(Out + ((size_t)z * M + m) * N + n) = v;
                } else {
                    float2 av = *(const float2*)(Obase + ((size_t)z * M + m) * DIM + n);
                    float* orow = Out + ((size_t)z * M + m) * OUTC + n;
                    *(float2*)(orow)           = av;
                    *(float2*)(orow + DIM)     = v;
                    *(float2*)(orow + 2*DIM)   = make_float2(av.x - v.x, av.y - v.y);
                    *(float2*)(orow + 3*DIM)   = make_float2(av.x * v.x, av.y * v.y);
                }
            }
        }
    }
}

// ---------------- bf16 split + transpose of fp32 input ----------------------
__global__ __launch_bounds__(256)
void conv_split_T(const float* __restrict__ X,
                  __nv_bfloat16* __restrict__ Xh,  __nv_bfloat16* __restrict__ Xl,
                  __nv_bfloat16* __restrict__ XTh, __nv_bfloat16* __restrict__ XTl,
                  int R, int C)
{
    __shared__ __nv_bfloat16 sh[64][65], sl[64][65];
    int z = blockIdx.z, r0 = blockIdx.y * 64, c0 = blockIdx.x * 64;
    #pragma unroll
    for (int it = 0; it < 16; it++) {
        int idx = threadIdx.x + it * 256;
        int i = idx >> 6, j = idx & 63;
        float v = X[((size_t)z * R + r0 + i) * C + c0 + j];
        __nv_bfloat16 h = __float2bfloat16(v);
        __nv_bfloat16 l = __float2bfloat16(v - __bfloat162float(h));
        Xh[((size_t)z * R + r0 + i) * C + c0 + j] = h;
        Xl[((size_t)z * R + r0 + i) * C + c0 + j] = l;
        sh[i][j] = h; sl[i][j] = l;
    }
    __syncthreads();
    #pragma unroll
    for (int it = 0; it < 16; it++) {
        int idx = threadIdx.x + it * 256;
        int j = idx >> 6, i = idx & 63;
        XTh[((size_t)z * C + c0 + j) * R + r0 + i] = sh[i][j];
        XTl[((size_t)z * C + c0 + j) * R + r0 + i] = sl[i][j];
    }
}

// ---------------- row softmax (axis=2) -> bf16 split P_a --------------------
__global__ __launch_bounds__(256)
void row_softmax_k(const float* __restrict__ e,
                   __nv_bfloat16* __restrict__ ph, __nv_bfloat16* __restrict__ pl)
{
    __shared__ float red[256];
    const float* p = e + (size_t)blockIdx.x * LB;
    int t = threadIdx.x;
    float v0 = p[t], v1 = p[t + 256];
    red[t] = fmaxf(v0, v1);
    __syncthreads();
    #pragma unroll
    for (int s = 128; s; s >>= 1) { if (t < s) red[t] = fmaxf(red[t], red[t + s]); __syncthreads(); }
    float m = red[0];
    __syncthreads();
    float e0 = __expf(v0 - m), e1 = __expf(v1 - m);
    red[t] = e0 + e1;
    __syncthreads();
    #pragma unroll
    for (int s = 128; s; s >>= 1) { if (t < s) red[t] += red[t + s]; __syncthreads(); }
    float inv = 1.f / red[0];
    float q0 = e0 * inv, q1 = e1 * inv;
    __nv_bfloat16 h0 = __float2bfloat16(q0), h1 = __float2bfloat16(q1);
    size_t base = (size_t)blockIdx.x * LB;
    ph[base + t] = h0;       pl[base + t]       = __float2bfloat16(q0 - __bfloat162float(h0));
    ph[base + t + 256] = h1; pl[base + t + 256] = __float2bfloat16(q1 - __bfloat162float(h1));
}

// ---------------- column stats (axis=1 softmax denom) ------------------------
__global__ __launch_bounds__(256)
void col_stats_k(const float* __restrict__ e, float* __restrict__ cmax, float* __restrict__ cinv)
{
    int z = blockIdx.y;
    int c = blockIdx.x * 256 + threadIdx.x;
    const float* base = e + (size_t)z * LA * LB + c;
    float m = -3.4e38f, s = 0.f;
    for (int a = 0; a < LA; a++) {
        float v = base[(size_t)a * LB];
        if (v > m) { s = s * __expf(m - v) + 1.f; m = v; }
        else       { s += __expf(v - m); }
    }
    cmax[z * LB + c] = m;
    cinv[z * LB + c] = 1.f / s;
}

// ---------------- column softmax + transpose -> bf16 split P_b^T ------------
__global__ __launch_bounds__(256)
void col_trans_k(const float* __restrict__ e, const float* __restrict__ cmax,
                 const float* __restrict__ cinv,
                 __nv_bfloat16* __restrict__ pbh, __nv_bfloat16* __restrict__ pbl)
{
    __shared__ float sp[64][65];
    int z = blockIdx.z, a0 = blockIdx.y * 64, c0 = blockIdx.x * 64;
    #pragma unroll
    for (int it = 0; it < 16; it++) {
        int idx = threadIdx.x + it * 256;
        int i = idx >> 6, j = idx & 63;      // i = a, j = c
        float v = e[((size_t)z * LA + a0 + i) * LB + c0 + j];
        sp[i][j] = __expf(v - cmax[z * LB + c0 + j]) * cinv[z * LB + c0 + j];
    }
    __syncthreads();
    #pragma unroll
    for (int it = 0; it < 16; it++) {
        int idx = threadIdx.x + it * 256;
        int j = idx >> 6, i = idx & 63;      // out row = c0+j, col = a0+i
        float q = sp[i][j];
        __nv_bfloat16 h = __float2bfloat16(q);
        pbh[((size_t)z * LB + c0 + j) * LA + a0 + i] = h;
        pbl[((size_t)z * LB + c0 + j) * LA + a0 + i] = __float2bfloat16(q - __bfloat162float(h));
    }
}

// ---------------------------------------------------------------------------
extern "C" void kernel_launch(void* const* d_in, const int* in_sizes, int n_in,
                              void* d_out, int out_size)
{
    const float* a_bar = (const float*)d_in[0];
    const float* b_bar = (const float*)d_in[1];
    float* out = (float*)d_out;
    float* m_a = out;
    float* m_b = out + (size_t)NB * LA * OUTC;

    __nv_bfloat16 *ah, *al, *bh, *bl, *aTh, *aTl, *bTh, *bTl, *ph, *pl, *pbh, *pbl;
    float *pe, *pcm, *pci;
    cudaGetSymbolAddress((void**)&ah,  g_ah);   cudaGetSymbolAddress((void**)&al,  g_al);
    cudaGetSymbolAddress((void**)&bh,  g_bh);   cudaGetSymbolAddress((void**)&bl,  g_bl);
    cudaGetSymbolAddress((void**)&aTh, g_aTh);  cudaGetSymbolAddress((void**)&aTl, g_aTl);
    cudaGetSymbolAddress((void**)&bTh, g_bTh);  cudaGetSymbolAddress((void**)&bTl, g_bTl);
    cudaGetSymbolAddress((void**)&ph,  g_ph);   cudaGetSymbolAddress((void**)&pl,  g_pl);
    cudaGetSymbolAddress((void**)&pbh, g_pbTh); cudaGetSymbolAddress((void**)&pbl, g_pbTl);
    cudaGetSymbolAddress((void**)&pe,  g_e);
    cudaGetSymbolAddress((void**)&pcm, g_cmax); cudaGetSymbolAddress((void**)&pci, g_cinv);

    cudaFuncSetAttribute(gemm_hmma<0>, cudaFuncAttributeMaxDynamicSharedMemorySize, SMEM_DYN);
    cudaFuncSetAttribute(gemm_hmma<1>, cudaFuncAttributeMaxDynamicSharedMemorySize, SMEM_DYN);

    // 1) bf16 split + transposed copies of inputs
    conv_split_T<<<dim3(DIM/64, LA/64, NB), 256>>>(a_bar, ah, al, aTh, aTl, LA, DIM);
    conv_split_T<<<dim3(DIM/64, LB/64, NB), 256>>>(b_bar, bh, bl, bTh, bTl, LB, DIM);

    // 2) e = a @ b^T   (M=LA, N=LB, K=DIM)
    gemm_hmma<0><<<dim3(LB/128, LA/128, NB), 256, SMEM_DYN>>>(
        ah, al, bh, bl, nullptr, pe, LA, LB, DIM);

    // 3) softmaxes -> split P_a [a,c] and P_b^T [c,a]
    row_softmax_k<<<NB * LA, 256>>>(pe, ph, pl);
    col_stats_k<<<dim3(LB/256, NB), 256>>>(pe, pcm, pci);
    col_trans_k<<<dim3(LB/64, LA/64, NB), 256>>>(pe, pcm, pci, pbh, pbl);

    // 4) a_tilde = P_a @ b  (M=LA, N=DIM, K=LB), fused m_a assembly
    gemm_hmma<1><<<dim3(DIM/128, LA/128, NB), 256, SMEM_DYN>>>(
        ph, pl, bTh, bTl, a_bar, m_a, LA, DIM, LB);

    // 5) b_tilde = P_b^T @ a (M=LB, N=DIM, K=LA), fused m_b assembly
    gemm_hmma<1><<<dim3(DIM/128, LB/128, NB), 256, SMEM_DYN>>>(
        pbh, pbl, aTh, aTl, b_bar, m_b, LB, DIM, LA);
}

// round 5
// speedup vs baseline: 1.1997x; 1.1997x over previous
#include <cuda_runtime.h>
#include <cuda_fp16.h>
#include <cstdint>

#define NB   32
#define LA   512
#define LB   512
#define DIM  768
#define OUTC 3072

// ---------------- scratch (__device__ globals; no allocation allowed) -------
__device__ __align__(1024) __half g_ah [(size_t)NB*LA*DIM], g_al [(size_t)NB*LA*DIM];
__device__ __align__(1024) __half g_bh [(size_t)NB*LB*DIM], g_bl [(size_t)NB*LB*DIM];
__device__ __align__(1024) __half g_aTh[(size_t)NB*DIM*LA], g_aTl[(size_t)NB*DIM*LA];
__device__ __align__(1024) __half g_bTh[(size_t)NB*DIM*LB], g_bTl[(size_t)NB*DIM*LB];
__device__ __align__(1024) __half g_ph [(size_t)NB*LA*LB];
__device__ __align__(1024) __half g_pbT[(size_t)NB*LB*LA];
__device__ __align__(1024) float g_e[(size_t)NB*LA*LB];
__device__ float g_cmax[NB*LB], g_cinv[NB*LB];

// ---------------- low-level helpers (portable PTX only) ---------------------
__device__ __forceinline__ uint32_t smem_to_u32(const void* p) {
    uint32_t a;
    asm("{ .reg .u64 t; cvta.to.shared.u64 t, %1; cvt.u32.u64 %0, t; }" : "=r"(a) : "l"(p));
    return a;
}
__device__ __forceinline__ void cp16(uint32_t dst, const void* src) {
    asm volatile("cp.async.cg.shared.global [%0], [%1], 16;" :: "r"(dst), "l"(src));
}
__device__ __forceinline__ void cp_commit() { asm volatile("cp.async.commit_group;"); }
__device__ __forceinline__ void cp_wait1()  { asm volatile("cp.async.wait_group 1;"); }

__device__ __forceinline__ void ldsm4(uint32_t* r, uint32_t addr) {
    asm volatile("ldmatrix.sync.aligned.m8n8.x4.shared.b16 {%0,%1,%2,%3}, [%4];"
                 : "=r"(r[0]), "=r"(r[1]), "=r"(r[2]), "=r"(r[3]) : "r"(addr));
}
__device__ __forceinline__ void mma_f16(float* c, const uint32_t* a, const uint32_t* b) {
    asm volatile("mma.sync.aligned.m16n8k16.row.col.f32.f16.f16.f32 "
                 "{%0,%1,%2,%3}, {%4,%5,%6,%7}, {%8,%9}, {%0,%1,%2,%3};"
                 : "+f"(c[0]), "+f"(c[1]), "+f"(c[2]), "+f"(c[3])
                 : "r"(a[0]), "r"(a[1]), "r"(a[2]), "r"(a[3]), "r"(b[0]), "r"(b[1]));
}

// ---------------- split-fp16 HMMA GEMM ---------------------------------------
// SPLITA=true : C = (Ah+Al)(Bh+Bl)^T, 3 passes (hh, hl, lh)
// SPLITA=false: C = A (Bh+Bl)^T, A single fp16 (softmax P), 2 passes
// CTA tile 128x128, BK=32, 8 warps (2 M x 4 N), warp tile 64x32.
#define TILE_BYTES 8192            // 128 rows x 32 cols x 2B

template<int MODE, bool SPLITA>   // MODE 0: plain fp32 store; 1: ESIM epilogue
__global__ __launch_bounds__(256)
void gemm_hmma(const __half* __restrict__ Ah, const __half* __restrict__ Al,
               const __half* __restrict__ Bh, const __half* __restrict__ Bl,
               const float* __restrict__ Obase, float* __restrict__ Out,
               int M, int N, int K)
{
    constexpr int NT = SPLITA ? 4 : 3;
    constexpr int STAGE = NT * TILE_BYTES;

    extern __shared__ char smraw[];
    uint32_t sm0 = smem_to_u32(smraw);
    uint32_t smb = (sm0 + 1023u) & ~1023u;

    const int tid = threadIdx.x;
    const int lid = tid & 31, wid = tid >> 5;
    const int wm = wid >> 2, wn = wid & 3;            // 2 x 4 warp grid
    const int z = blockIdx.z, m0 = blockIdx.y * 128, n0 = blockIdx.x * 128;

    const __half* srcs[4];
    if (SPLITA) {
        srcs[0] = Ah + ((size_t)z * M + m0) * K;
        srcs[1] = Al + ((size_t)z * M + m0) * K;
        srcs[2] = Bh + ((size_t)z * N + n0) * K;
        srcs[3] = Bl + ((size_t)z * N + n0) * K;
    } else {
        srcs[0] = Ah + ((size_t)z * M + m0) * K;
        srcs[1] = Bh + ((size_t)z * N + n0) * K;
        srcs[2] = Bl + ((size_t)z * N + n0) * K;
        srcs[3] = nullptr;
    }

    // precompute ldmatrix lane offsets
    const int ar  = (lid & 7) | (((lid >> 3) & 1) << 3);   // 0..15 row-in-tile16
    const int akh = lid >> 4;
    uint32_t aoff[4];
    #pragma unroll
    for (int i = 0; i < 4; i++) {
        int m = wm * 64 + i * 16 + ar;
        aoff[i] = m * 32 + ((akh ^ ((m >> 2) & 1)) << 4);
    }
    const int br  = (lid & 7) | ((lid >> 4) << 3);
    const int bkh = (lid >> 3) & 1;
    uint32_t boff[2];
    #pragma unroll
    for (int j2 = 0; j2 < 2; j2++) {
        int n = wn * 32 + j2 * 16 + br;
        boff[j2] = n * 32 + ((bkh ^ ((n >> 2) & 1)) << 4);
    }

    float acc[4][4][4];
    #pragma unroll
    for (int i = 0; i < 4; i++)
        #pragma unroll
        for (int j = 0; j < 4; j++)
            #pragma unroll
            for (int r = 0; r < 4; r++) acc[i][j][r] = 0.f;

    const int nk = K >> 5;   // K / 32

    auto issue_stage = [&](int s, int kt) {
        uint32_t sb = smb + s * STAGE;
        #pragma unroll
        for (int tl = 0; tl < NT; tl++) {
            const __half* src = srcs[tl];
            uint32_t tb = sb + tl * TILE_BYTES;
            #pragma unroll
            for (int it = 0; it < 2; it++) {
                int idx = tid + it * 256;          // 0..511
                int m  = idx >> 2;
                int ks = (idx >> 1) & 1;
                int kh = idx & 1;
                uint32_t d = tb + ks * 4096 + m * 32 + ((kh ^ ((m >> 2) & 1)) << 4);
                cp16(d, src + (size_t)m * K + kt * 32 + ks * 16 + kh * 8);
            }
        }
    };

    issue_stage(0, 0);
    cp_commit();

    for (int kt = 0; kt < nk; kt++) {
        if (kt + 1 < nk) issue_stage((kt + 1) & 1, kt + 1);
        cp_commit();
        cp_wait1();
        __syncthreads();

        uint32_t st = smb + (kt & 1) * STAGE;
        #pragma unroll
        for (int ks = 0; ks < 2; ks++) {
            if (SPLITA) {
                uint32_t a_h[4][4], a_l[4][4], b_h[4][2], b_l[4][2];
                #pragma unroll
                for (int i = 0; i < 4; i++) {
                    ldsm4(a_h[i], st + 0 * TILE_BYTES + ks * 4096 + aoff[i]);
                    ldsm4(a_l[i], st + 1 * TILE_BYTES + ks * 4096 + aoff[i]);
                }
                #pragma unroll
                for (int j2 = 0; j2 < 2; j2++) {
                    uint32_t rh[4], rl[4];
                    ldsm4(rh, st + 2 * TILE_BYTES + ks * 4096 + boff[j2]);
                    ldsm4(rl, st + 3 * TILE_BYTES + ks * 4096 + boff[j2]);
                    b_h[j2*2+0][0] = rh[0]; b_h[j2*2+0][1] = rh[1];
                    b_h[j2*2+1][0] = rh[2]; b_h[j2*2+1][1] = rh[3];
                    b_l[j2*2+0][0] = rl[0]; b_l[j2*2+0][1] = rl[1];
                    b_l[j2*2+1][0] = rl[2]; b_l[j2*2+1][1] = rl[3];
                }
                #pragma unroll
                for (int i = 0; i < 4; i++)
                    #pragma unroll
                    for (int j = 0; j < 4; j++)
                        mma_f16(acc[i][j], a_h[i], b_h[j]);
                #pragma unroll
                for (int i = 0; i < 4; i++)
                    #pragma unroll
                    for (int j = 0; j < 4; j++)
                        mma_f16(acc[i][j], a_h[i], b_l[j]);
                #pragma unroll
                for (int i = 0; i < 4; i++)
                    #pragma unroll
                    for (int j = 0; j < 4; j++)
                        mma_f16(acc[i][j], a_l[i], b_h[j]);
            } else {
                uint32_t a_f[4][4], b_h[4][2], b_l[4][2];
                #pragma unroll
                for (int i = 0; i < 4; i++)
                    ldsm4(a_f[i], st + 0 * TILE_BYTES + ks * 4096 + aoff[i]);
                #pragma unroll
                for (int j2 = 0; j2 < 2; j2++) {
                    uint32_t rh[4], rl[4];
                    ldsm4(rh, st + 1 * TILE_BYTES + ks * 4096 + boff[j2]);
                    ldsm4(rl, st + 2 * TILE_BYTES + ks * 4096 + boff[j2]);
                    b_h[j2*2+0][0] = rh[0]; b_h[j2*2+0][1] = rh[1];
                    b_h[j2*2+1][0] = rh[2]; b_h[j2*2+1][1] = rh[3];
                    b_l[j2*2+0][0] = rl[0]; b_l[j2*2+0][1] = rl[1];
                    b_l[j2*2+1][0] = rl[2]; b_l[j2*2+1][1] = rl[3];
                }
                #pragma unroll
                for (int i = 0; i < 4; i++)
                    #pragma unroll
                    for (int j = 0; j < 4; j++)
                        mma_f16(acc[i][j], a_f[i], b_h[j]);
                #pragma unroll
                for (int i = 0; i < 4; i++)
                    #pragma unroll
                    for (int j = 0; j < 4; j++)
                        mma_f16(acc[i][j], a_f[i], b_l[j]);
            }
        }
        __syncthreads();
    }

    // ---- epilogue: fragments -> global (32B sector stores) ----
    const int g = lid >> 2, t = lid & 3;
    #pragma unroll
    for (int i = 0; i < 4; i++) {
        #pragma unroll
        for (int j = 0; j < 4; j++) {
            int n = n0 + wn * 32 + j * 8 + t * 2;
            #pragma unroll
            for (int half = 0; half < 2; half++) {
                int m = m0 + wm * 64 + i * 16 + g + half * 8;
                float2 v = make_float2(acc[i][j][half*2+0], acc[i][j][half*2+1]);
                if (MODE == 0) {
                    *(float2*)(Out + ((size_t)z * M + m) * N + n) = v;
                } else {
                    float2 av = *(const float2*)(Obase + ((size_t)z * M + m) * DIM + n);
                    float* orow = Out + ((size_t)z * M + m) * OUTC + n;
                    *(float2*)(orow)           = av;
                    *(float2*)(orow + DIM)     = v;
                    *(float2*)(orow + 2*DIM)   = make_float2(av.x - v.x, av.y - v.y);
                    *(float2*)(orow + 3*DIM)   = make_float2(av.x * v.x, av.y * v.y);
                }
            }
        }
    }
}

// ---------------- fp16 split + transpose of fp32 input ----------------------
__global__ __launch_bounds__(256)
void conv_split_T(const float* __restrict__ X,
                  __half* __restrict__ Xh,  __half* __restrict__ Xl,
                  __half* __restrict__ XTh, __half* __restrict__ XTl,
                  int R, int C)
{
    __shared__ __half sh[64][65], sl[64][65];
    int z = blockIdx.z, r0 = blockIdx.y * 64, c0 = blockIdx.x * 64;
    #pragma unroll
    for (int it = 0; it < 16; it++) {
        int idx = threadIdx.x + it * 256;
        int i = idx >> 6, j = idx & 63;
        float v = X[((size_t)z * R + r0 + i) * C + c0 + j];
        __half h = __float2half_rn(v);
        __half l = __float2half_rn(v - __half2float(h));
        Xh[((size_t)z * R + r0 + i) * C + c0 + j] = h;
        Xl[((size_t)z * R + r0 + i) * C + c0 + j] = l;
        sh[i][j] = h; sl[i][j] = l;
    }
    __syncthreads();
    #pragma unroll
    for (int it = 0; it < 16; it++) {
        int idx = threadIdx.x + it * 256;
        int j = idx >> 6, i = idx & 63;
        XTh[((size_t)z * C + c0 + j) * R + r0 + i] = sh[i][j];
        XTl[((size_t)z * C + c0 + j) * R + r0 + i] = sl[i][j];
    }
}

// ---------------- row softmax (axis=2) -> fp16 P_a --------------------------
__global__ __launch_bounds__(256)
void row_softmax_k(const float* __restrict__ e, __half* __restrict__ ph)
{
    __shared__ float red[256];
    const float* p = e + (size_t)blockIdx.x * LB;
    int t = threadIdx.x;
    float v0 = p[t], v1 = p[t + 256];
    red[t] = fmaxf(v0, v1);
    __syncthreads();
    #pragma unroll
    for (int s = 128; s; s >>= 1) { if (t < s) red[t] = fmaxf(red[t], red[t + s]); __syncthreads(); }
    float m = red[0];
    __syncthreads();
    float e0 = __expf(v0 - m), e1 = __expf(v1 - m);
    red[t] = e0 + e1;
    __syncthreads();
    #pragma unroll
    for (int s = 128; s; s >>= 1) { if (t < s) red[t] += red[t + s]; __syncthreads(); }
    float inv = 1.f / red[0];
    size_t base = (size_t)blockIdx.x * LB;
    ph[base + t]       = __float2half_rn(e0 * inv);
    ph[base + t + 256] = __float2half_rn(e1 * inv);
}

// ---------------- column stats (axis=1 softmax denom) ------------------------
__global__ __launch_bounds__(256)
void col_stats_k(const float* __restrict__ e, float* __restrict__ cmax, float* __restrict__ cinv)
{
    int z = blockIdx.y;
    int c = blockIdx.x * 256 + threadIdx.x;
    const float* base = e + (size_t)z * LA * LB + c;
    float m = -3.4e38f, s = 0.f;
    for (int a = 0; a < LA; a++) {
        float v = base[(size_t)a * LB];
        if (v > m) { s = s * __expf(m - v) + 1.f; m = v; }
        else       { s += __expf(v - m); }
    }
    cmax[z * LB + c] = m;
    cinv[z * LB + c] = 1.f / s;
}

// ---------------- column softmax + transpose -> fp16 P_b^T ------------------
__global__ __launch_bounds__(256)
void col_trans_k(const float* __restrict__ e, const float* __restrict__ cmax,
                 const float* __restrict__ cinv, __half* __restrict__ pbT)
{
    __shared__ float sp[64][65];
    int z = blockIdx.z, a0 = blockIdx.y * 64, c0 = blockIdx.x * 64;
    #pragma unroll
    for (int it = 0; it < 16; it++) {
        int idx = threadIdx.x + it * 256;
        int i = idx >> 6, j = idx & 63;      // i = a, j = c
        float v = e[((size_t)z * LA + a0 + i) * LB + c0 + j];
        sp[i][j] = __expf(v - cmax[z * LB + c0 + j]) * cinv[z * LB + c0 + j];
    }
    __syncthreads();
    #pragma unroll
    for (int it = 0; it < 16; it++) {
        int idx = threadIdx.x + it * 256;
        int j = idx >> 6, i = idx & 63;      // out row = c0+j, col = a0+i
        pbT[((size_t)z * LB + c0 + j) * LA + a0 + i] = __float2half_rn(sp[i][j]);
    }
}

// ---------------------------------------------------------------------------
extern "C" void kernel_launch(void* const* d_in, const int* in_sizes, int n_in,
                              void* d_out, int out_size)
{
    const float* a_bar = (const float*)d_in[0];
    const float* b_bar = (const float*)d_in[1];
    float* out = (float*)d_out;
    float* m_a = out;
    float* m_b = out + (size_t)NB * LA * OUTC;

    __half *ah, *al, *bh, *bl, *aTh, *aTl, *bTh, *bTl, *ph, *pbT;
    float *pe, *pcm, *pci;
    cudaGetSymbolAddress((void**)&ah,  g_ah);   cudaGetSymbolAddress((void**)&al,  g_al);
    cudaGetSymbolAddress((void**)&bh,  g_bh);   cudaGetSymbolAddress((void**)&bl,  g_bl);
    cudaGetSymbolAddress((void**)&aTh, g_aTh);  cudaGetSymbolAddress((void**)&aTl, g_aTl);
    cudaGetSymbolAddress((void**)&bTh, g_bTh);  cudaGetSymbolAddress((void**)&bTl, g_bTl);
    cudaGetSymbolAddress((void**)&ph,  g_ph);   cudaGetSymbolAddress((void**)&pbT, g_pbT);
    cudaGetSymbolAddress((void**)&pe,  g_e);
    cudaGetSymbolAddress((void**)&pcm, g_cmax); cudaGetSymbolAddress((void**)&pci, g_cinv);

    constexpr int SMEM4 = 2 * 4 * TILE_BYTES + 1024;   // 3-pass stages
    constexpr int SMEM3 = 2 * 3 * TILE_BYTES + 1024;   // 2-pass stages
    cudaFuncSetAttribute(gemm_hmma<0, true>,  cudaFuncAttributeMaxDynamicSharedMemorySize, SMEM4);
    cudaFuncSetAttribute(gemm_hmma<1, false>, cudaFuncAttributeMaxDynamicSharedMemorySize, SMEM3);

    // 1) fp16 split + transposed copies of inputs
    conv_split_T<<<dim3(DIM/64, LA/64, NB), 256>>>(a_bar, ah, al, aTh, aTl, LA, DIM);
    conv_split_T<<<dim3(DIM/64, LB/64, NB), 256>>>(b_bar, bh, bl, bTh, bTl, LB, DIM);

    // 2) e = a @ b^T   (M=LA, N=LB, K=DIM), 3-pass split GEMM
    gemm_hmma<0, true><<<dim3(LB/128, LA/128, NB), 256, SMEM4>>>(
        ah, al, bh, bl, nullptr, pe, LA, LB, DIM);

    // 3) softmaxes -> fp16 P_a [a,c] and P_b^T [c,a]
    row_softmax_k<<<NB * LA, 256>>>(pe, ph);
    col_stats_k<<<dim3(LB/256, NB), 256>>>(pe, pcm, pci);
    col_trans_k<<<dim3(LB/64, LA/64, NB), 256>>>(pe, pcm, pci, pbT);

    // 4) a_tilde = P_a @ b  (M=LA, N=DIM, K=LB), 2-pass, fused m_a assembly
    gemm_hmma<1, false><<<dim3(DIM/128, LA/128, NB), 256, SMEM3>>>(
        ph, nullptr, bTh, bTl, a_bar, m_a, LA, DIM, LB);

    // 5) b_tilde = P_b^T @ a (M=LB, N=DIM, K=LA), 2-pass, fused m_b assembly
    gemm_hmma<1, false><<<dim3(DIM/128, LB/128, NB), 256, SMEM3>>>(
        pbT, nullptr, aTh, aTl, b_bar, m_b, LB, DIM, LA);
}

// round 6
// speedup vs baseline: 1.3435x; 1.1199x over previous
#include <cuda_runtime.h>
#include <cuda_fp16.h>
#include <cstdint>

#define NB   32
#define LA   512
#define LB   512
#define DIM  768
#define OUTC 3072
#define NROW (NB*512)   // 16384 scalar slots

// ---------------- scratch (__device__ globals; no allocation allowed) -------
__device__ __align__(1024) __half g_ah [(size_t)NB*LA*DIM], g_al [(size_t)NB*LA*DIM];
__device__ __align__(1024) __half g_bh [(size_t)NB*LB*DIM], g_bl [(size_t)NB*LB*DIM];
__device__ __align__(1024) __half g_aTh[(size_t)NB*DIM*LA], g_aTl[(size_t)NB*DIM*LA];
__device__ __align__(1024) __half g_bTh[(size_t)NB*DIM*LB], g_bTl[(size_t)NB*DIM*LB];
__device__ __align__(1024) float g_e[(size_t)NB*LA*LB];
// partial stats: [4 blocks][NB*512]
__device__ float g_rpmax[4*NROW], g_rpsum[4*NROW];
__device__ float g_cpmax[4*NROW], g_cpsum[4*NROW];
// reduced scalars
__device__ float g_rowm[NROW], g_rowi[NROW], g_colm[NROW], g_coli[NROW];

// ---------------- low-level helpers (portable PTX only) ---------------------
__device__ __forceinline__ uint32_t smem_to_u32(const void* p) {
    uint32_t a;
    asm("{ .reg .u64 t; cvta.to.shared.u64 t, %1; cvt.u32.u64 %0, t; }" : "=r"(a) : "l"(p));
    return a;
}
__device__ __forceinline__ void cp16(uint32_t dst, const void* src) {
    asm volatile("cp.async.cg.shared.global [%0], [%1], 16;" :: "r"(dst), "l"(src));
}
__device__ __forceinline__ void cp_commit() { asm volatile("cp.async.commit_group;"); }
__device__ __forceinline__ void cp_wait1()  { asm volatile("cp.async.wait_group 1;"); }
__device__ __forceinline__ void cp_wait0()  { asm volatile("cp.async.wait_group 0;"); }

__device__ __forceinline__ void ldsm4(uint32_t* r, uint32_t addr) {
    asm volatile("ldmatrix.sync.aligned.m8n8.x4.shared.b16 {%0,%1,%2,%3}, [%4];"
                 : "=r"(r[0]), "=r"(r[1]), "=r"(r[2]), "=r"(r[3]) : "r"(addr));
}
__device__ __forceinline__ void mma_f16(float* c, const uint32_t* a, const uint32_t* b) {
    asm volatile("mma.sync.aligned.m16n8k16.row.col.f32.f16.f16.f32 "
                 "{%0,%1,%2,%3}, {%4,%5,%6,%7}, {%8,%9}, {%0,%1,%2,%3};"
                 : "+f"(c[0]), "+f"(c[1]), "+f"(c[2]), "+f"(c[3])
                 : "r"(a[0]), "r"(a[1]), "r"(a[2]), "r"(a[3]), "r"(b[0]), "r"(b[1]));
}

#define TILE_BYTES 8192            // 128 rows x 32 halfs (2 ks-halves of 16)

// swizzled smem byte offset inside a tile for (row, 16B-chunk kh)
__device__ __forceinline__ uint32_t sw_off(int row, int kh) {
    return (uint32_t)(row * 32 + ((kh ^ ((row >> 2) & 1)) << 4));
}

// =============================================================================
// GEMM1: e = (Ah+Al)(Bh+Bl)^T, 3 passes, fp32 e store + row/col partial stats.
// CTA 128x128, 8 warps (2M x 4N), warp tile 64x32, BK=32 double buffered.
// =============================================================================
#define G1_STAGE (4*TILE_BYTES)
#define G1_SCRATCH 8192
#define G1_SMEM (2*G1_STAGE + G1_SCRATCH + 1024)

__global__ __launch_bounds__(256)
void gemm1_k(const __half* __restrict__ Ah, const __half* __restrict__ Al,
             const __half* __restrict__ Bh, const __half* __restrict__ Bl,
             float* __restrict__ E)
{
    extern __shared__ char smraw[];
    uint32_t sm0 = smem_to_u32(smraw);
    uint32_t smb = (sm0 + 1023u) & ~1023u;
    char* smc = smraw + (smb - sm0);

    const int tid = threadIdx.x;
    const int lid = tid & 31, wid = tid >> 5;
    const int wm = wid >> 2, wn = wid & 3;
    const int g = lid >> 2, t = lid & 3;
    const int z = blockIdx.z, m0 = blockIdx.y * 128, n0 = blockIdx.x * 128;
    const int K = DIM;

    const __half* srcs[4] = {
        Ah + ((size_t)z * LA + m0) * K, Al + ((size_t)z * LA + m0) * K,
        Bh + ((size_t)z * LB + n0) * K, Bl + ((size_t)z * LB + n0) * K };

    const int ar  = (lid & 7) | (((lid >> 3) & 1) << 3);
    const int akh = lid >> 4;
    uint32_t aoff[4];
    #pragma unroll
    for (int i = 0; i < 4; i++)
        aoff[i] = sw_off(wm * 64 + i * 16 + ar, akh);
    const int br  = (lid & 7) | ((lid >> 4) << 3);
    const int bkh = (lid >> 3) & 1;
    uint32_t boff[2];
    #pragma unroll
    for (int j2 = 0; j2 < 2; j2++)
        boff[j2] = sw_off(wn * 32 + j2 * 16 + br, bkh);

    float acc[4][4][4];
    #pragma unroll
    for (int i = 0; i < 4; i++)
        #pragma unroll
        for (int j = 0; j < 4; j++)
            #pragma unroll
            for (int r = 0; r < 4; r++) acc[i][j][r] = 0.f;

    const int nk = K >> 5;

    auto issue_stage = [&](int s, int kt) {
        uint32_t sb = smb + s * G1_STAGE;
        #pragma unroll
        for (int tl = 0; tl < 4; tl++) {
            const __half* src = srcs[tl];
            uint32_t tb = sb + tl * TILE_BYTES;
            #pragma unroll
            for (int it = 0; it < 2; it++) {
                int idx = tid + it * 256;
                int m = idx >> 2, ks = (idx >> 1) & 1, kh = idx & 1;
                cp16(tb + ks * 4096 + sw_off(m, kh),
                     src + (size_t)m * K + kt * 32 + ks * 16 + kh * 8);
            }
        }
    };

    issue_stage(0, 0);
    cp_commit();

    for (int kt = 0; kt < nk; kt++) {
        if (kt + 1 < nk) { issue_stage((kt + 1) & 1, kt + 1); }
        cp_commit();
        cp_wait1();
        __syncthreads();

        uint32_t st = smb + (kt & 1) * G1_STAGE;
        #pragma unroll
        for (int ks = 0; ks < 2; ks++) {
            uint32_t a_h[4][4], a_l[4][4], b_h[4][2], b_l[4][2];
            #pragma unroll
            for (int i = 0; i < 4; i++) {
                ldsm4(a_h[i], st + 0 * TILE_BYTES + ks * 4096 + aoff[i]);
                ldsm4(a_l[i], st + 1 * TILE_BYTES + ks * 4096 + aoff[i]);
            }
            #pragma unroll
            for (int j2 = 0; j2 < 2; j2++) {
                uint32_t rh[4], rl[4];
                ldsm4(rh, st + 2 * TILE_BYTES + ks * 4096 + boff[j2]);
                ldsm4(rl, st + 3 * TILE_BYTES + ks * 4096 + boff[j2]);
                b_h[j2*2+0][0] = rh[0]; b_h[j2*2+0][1] = rh[1];
                b_h[j2*2+1][0] = rh[2]; b_h[j2*2+1][1] = rh[3];
                b_l[j2*2+0][0] = rl[0]; b_l[j2*2+0][1] = rl[1];
                b_l[j2*2+1][0] = rl[2]; b_l[j2*2+1][1] = rl[3];
            }
            #pragma unroll
            for (int i = 0; i < 4; i++)
                #pragma unroll
                for (int j = 0; j < 4; j++) {
                    mma_f16(acc[i][j], a_h[i], b_h[j]);
                    mma_f16(acc[i][j], a_h[i], b_l[j]);
                    mma_f16(acc[i][j], a_l[i], b_h[j]);
                }
        }
        __syncthreads();
    }

    // ---- store e (fp32) ----
    #pragma unroll
    for (int i = 0; i < 4; i++)
        #pragma unroll
        for (int j = 0; j < 4; j++) {
            int n = n0 + wn * 32 + j * 8 + t * 2;
            #pragma unroll
            for (int h = 0; h < 2; h++) {
                int m = m0 + wm * 64 + i * 16 + g + h * 8;
                *(float2*)(E + ((size_t)z * LA + m) * LB + n) =
                    make_float2(acc[i][j][h*2+0], acc[i][j][h*2+1]);
            }
        }

    // ---- partial row/col softmax stats (on-chip) ----
    __syncthreads();
    float* scr   = (float*)(smc + 2 * G1_STAGE);
    float* srmax = scr;            // [128][4]
    float* srsum = scr + 512;      // [128][4]
    float* srm   = scr + 1024;     // [128]
    float* scmax = scr + 1152;     // [128][2]
    float* scsum = scr + 1408;     // [128][2]
    float* scm   = scr + 1664;     // [128]

    // row partial max
    #pragma unroll
    for (int i = 0; i < 4; i++)
        #pragma unroll
        for (int h = 0; h < 2; h++) {
            float mv = -3.4e38f;
            #pragma unroll
            for (int j = 0; j < 4; j++) {
                mv = fmaxf(mv, acc[i][j][h*2+0]);
                mv = fmaxf(mv, acc[i][j][h*2+1]);
            }
            mv = fmaxf(mv, __shfl_xor_sync(0xFFFFFFFFu, mv, 1));
            mv = fmaxf(mv, __shfl_xor_sync(0xFFFFFFFFu, mv, 2));
            if (t == 0) srmax[(wm*64 + i*16 + g + h*8) * 4 + wn] = mv;
        }
    __syncthreads();
    if (tid < 128)
        srm[tid] = fmaxf(fmaxf(srmax[tid*4+0], srmax[tid*4+1]),
                         fmaxf(srmax[tid*4+2], srmax[tid*4+3]));
    __syncthreads();
    // row partial sum
    #pragma unroll
    for (int i = 0; i < 4; i++)
        #pragma unroll
        for (int h = 0; h < 2; h++) {
            int row = wm*64 + i*16 + g + h*8;
            float rm = srm[row], s = 0.f;
            #pragma unroll
            for (int j = 0; j < 4; j++) {
                s += __expf(acc[i][j][h*2+0] - rm);
                s += __expf(acc[i][j][h*2+1] - rm);
            }
            s += __shfl_xor_sync(0xFFFFFFFFu, s, 1);
            s += __shfl_xor_sync(0xFFFFFFFFu, s, 2);
            if (t == 0) srsum[row * 4 + wn] = s;
        }
    __syncthreads();
    if (tid < 128) {
        size_t o = (size_t)blockIdx.x * NROW + z * 512 + m0 + tid;
        g_rpmax[o] = srm[tid];
        g_rpsum[o] = srsum[tid*4+0] + srsum[tid*4+1] + srsum[tid*4+2] + srsum[tid*4+3];
    }

    // col partial max
    #pragma unroll
    for (int j = 0; j < 4; j++)
        #pragma unroll
        for (int rl = 0; rl < 2; rl++) {
            float mv = -3.4e38f;
            #pragma unroll
            for (int i = 0; i < 4; i++) {
                mv = fmaxf(mv, acc[i][j][rl]);
                mv = fmaxf(mv, acc[i][j][2+rl]);
            }
            mv = fmaxf(mv, __shfl_xor_sync(0xFFFFFFFFu, mv, 4));
            mv = fmaxf(mv, __shfl_xor_sync(0xFFFFFFFFu, mv, 8));
            mv = fmaxf(mv, __shfl_xor_sync(0xFFFFFFFFu, mv, 16));
            if (g == 0) scmax[(wn*32 + j*8 + t*2 + rl) * 2 + wm] = mv;
        }
    __syncthreads();
    if (tid < 128) scm[tid] = fmaxf(scmax[tid*2], scmax[tid*2+1]);
    __syncthreads();
    // col partial sum
    #pragma unroll
    for (int j = 0; j < 4; j++)
        #pragma unroll
        for (int rl = 0; rl < 2; rl++) {
            int col = wn*32 + j*8 + t*2 + rl;
            float cm = scm[col], s = 0.f;
            #pragma unroll
            for (int i = 0; i < 4; i++) {
                s += __expf(acc[i][j][rl] - cm);
                s += __expf(acc[i][j][2+rl] - cm);
            }
            s += __shfl_xor_sync(0xFFFFFFFFu, s, 4);
            s += __shfl_xor_sync(0xFFFFFFFFu, s, 8);
            s += __shfl_xor_sync(0xFFFFFFFFu, s, 16);
            if (g == 0) scsum[col * 2 + wm] = s;
        }
    __syncthreads();
    if (tid < 128) {
        size_t o = (size_t)blockIdx.y * NROW + z * 512 + n0 + tid;
        g_cpmax[o] = scm[tid];
        g_cpsum[o] = scsum[tid*2] + scsum[tid*2+1];
    }
}

// ---------------- reduce 4 partials -> max + 1/sum ---------------------------
__global__ __launch_bounds__(256)
void reduce_stats_k()
{
    int idx = blockIdx.x * 256 + threadIdx.x;   // 0..NROW-1
    const float* pm = blockIdx.y ? g_cpmax : g_rpmax;
    const float* ps = blockIdx.y ? g_cpsum : g_rpsum;
    float m = -3.4e38f;
    #pragma unroll
    for (int p = 0; p < 4; p++) m = fmaxf(m, pm[p * NROW + idx]);
    float s = 0.f;
    #pragma unroll
    for (int p = 0; p < 4; p++) s += ps[p * NROW + idx] * __expf(pm[p * NROW + idx] - m);
    if (blockIdx.y) { g_colm[idx] = m; g_coli[idx] = 1.f / s; }
    else            { g_rowm[idx] = m; g_rowi[idx] = 1.f / s; }
}

// =============================================================================
// GEMM_PV: C = P (Bh+Bl)^T where P = exp(e - m)*inv built on the fly (fp16).
// TRANSA=false: P rows = e rows (a). TRANSA=true: P rows = e cols (c).
// CTA 128x128, 8 warps (2Mx4N), warp 64x32. ESIM epilogue.
// =============================================================================
#define PV_STAGE (3*TILE_BYTES)
#define PV_SMEM (2*PV_STAGE + 2048)

template<bool TRANSA>
__global__ __launch_bounds__(256)
void gemm_pv(const float* __restrict__ E,
             const float* __restrict__ Msc, const float* __restrict__ Isc,
             const __half* __restrict__ Bh, const __half* __restrict__ Bl,
             const float* __restrict__ Obase, float* __restrict__ Out)
{
    const int M = 512, N = DIM, K = 512;
    extern __shared__ char smraw[];
    uint32_t sm0 = smem_to_u32(smraw);
    uint32_t smb = (sm0 + 1023u) & ~1023u;
    char* smc = smraw + (smb - sm0);

    const int tid = threadIdx.x;
    const int lid = tid & 31, wid = tid >> 5;
    const int wm = wid >> 2, wn = wid & 3;
    const int z = blockIdx.z, m0 = blockIdx.y * 128, n0 = blockIdx.x * 128;

    float* sm_m = (float*)(smc + 2 * PV_STAGE);
    float* sm_i = sm_m + 128;
    if (tid < 128) {
        sm_m[tid] = Msc[z * 512 + m0 + tid];
        sm_i[tid] = Isc[z * 512 + m0 + tid];
    }

    const __half* srcB[2] = { Bh + ((size_t)z * N + n0) * K,
                              Bl + ((size_t)z * N + n0) * K };

    const int ar  = (lid & 7) | (((lid >> 3) & 1) << 3);
    const int akh = lid >> 4;
    uint32_t aoff[4];
    #pragma unroll
    for (int i = 0; i < 4; i++)
        aoff[i] = sw_off(wm * 64 + i * 16 + ar, akh);
    const int br  = (lid & 7) | ((lid >> 4) << 3);
    const int bkh = (lid >> 3) & 1;
    uint32_t boff[2];
    #pragma unroll
    for (int j2 = 0; j2 < 2; j2++)
        boff[j2] = sw_off(wn * 32 + j2 * 16 + br, bkh);

    float acc[4][4][4];
    #pragma unroll
    for (int i = 0; i < 4; i++)
        #pragma unroll
        for (int j = 0; j < 4; j++)
            #pragma unroll
            for (int r = 0; r < 4; r++) acc[i][j][r] = 0.f;

    const int nk = K >> 5;   // 16

    auto issueB = [&](int s, int kt) {
        uint32_t sb = smb + s * PV_STAGE;
        #pragma unroll
        for (int tl = 0; tl < 2; tl++) {
            uint32_t tb = sb + (tl + 1) * TILE_BYTES;
            #pragma unroll
            for (int it = 0; it < 2; it++) {
                int idx = tid + it * 256;
                int m = idx >> 2, ks = (idx >> 1) & 1, kh = idx & 1;
                cp16(tb + ks * 4096 + sw_off(m, kh),
                     srcB[tl] + (size_t)m * K + kt * 32 + ks * 16 + kh * 8);
            }
        }
    };

    // build A tile (fp16 P) for chunk kt into stage s
    auto fillA = [&](int s, int kt) {
        char* tb = smc + s * PV_STAGE;   // A at offset 0
        if (!TRANSA) {
            #pragma unroll
            for (int it = 0; it < 4; it++) {
                int a = (tid >> 3) + it * 32;
                int c4 = (tid & 7) * 4;
                float4 v = *(const float4*)(E + ((size_t)z * M + m0 + a) * K + kt * 32 + c4);
                float rm = sm_m[a], ri = sm_i[a];
                __half2 h01 = __floats2half2_rn(__expf(v.x - rm) * ri, __expf(v.y - rm) * ri);
                __half2 h23 = __floats2half2_rn(__expf(v.z - rm) * ri, __expf(v.w - rm) * ri);
                int ks = c4 >> 4, within = c4 & 15;
                uint32_t off = (uint32_t)(ks * 4096) + sw_off(a, within >> 3) + (within & 7) * 2;
                *(__half2*)(tb + off)     = h01;
                *(__half2*)(tb + off + 4) = h23;
            }
        } else {
            int k4 = (tid >> 5) * 4;          // warp -> 4 k values
            #pragma unroll
            for (int it = 0; it < 4; it++) {
                int c = (tid & 31) + it * 32;
                float cm = sm_m[c], ci = sm_i[c];
                float p[4];
                #pragma unroll
                for (int ik = 0; ik < 4; ik++) {
                    float v = E[((size_t)z * 512 + kt * 32 + k4 + ik) * 512 + m0 + c];
                    p[ik] = __expf(v - cm) * ci;
                }
                __half2 h01 = __floats2half2_rn(p[0], p[1]);
                __half2 h23 = __floats2half2_rn(p[2], p[3]);
                int ks = k4 >> 4, within = k4 & 15;
                uint32_t off = (uint32_t)(ks * 4096) + sw_off(c, within >> 3) + (within & 7) * 2;
                *(__half2*)(tb + off)     = h01;
                *(__half2*)(tb + off + 4) = h23;
            }
        }
    };

    issueB(0, 0);
    cp_commit();
    __syncthreads();          // sm_m/sm_i ready
    fillA(0, 0);

    for (int kt = 0; kt < nk; kt++) {
        int s = kt & 1;
        if (kt + 1 < nk) { issueB(s ^ 1, kt + 1); cp_commit(); cp_wait1(); }
        else             { cp_wait0(); }
        __syncthreads();

        uint32_t st = smb + s * PV_STAGE;
        #pragma unroll
        for (int ks = 0; ks < 2; ks++) {
            uint32_t a_f[4][4], b_h[4][2], b_l[4][2];
            #pragma unroll
            for (int i = 0; i < 4; i++)
                ldsm4(a_f[i], st + ks * 4096 + aoff[i]);
            #pragma unroll
            for (int j2 = 0; j2 < 2; j2++) {
                uint32_t rh[4], rl[4];
                ldsm4(rh, st + 1 * TILE_BYTES + ks * 4096 + boff[j2]);
                ldsm4(rl, st + 2 * TILE_BYTES + ks * 4096 + boff[j2]);
                b_h[j2*2+0][0] = rh[0]; b_h[j2*2+0][1] = rh[1];
                b_h[j2*2+1][0] = rh[2]; b_h[j2*2+1][1] = rh[3];
                b_l[j2*2+0][0] = rl[0]; b_l[j2*2+0][1] = rl[1];
                b_l[j2*2+1][0] = rl[2]; b_l[j2*2+1][1] = rl[3];
            }
            #pragma unroll
            for (int i = 0; i < 4; i++)
                #pragma unroll
                for (int j = 0; j < 4; j++) {
                    mma_f16(acc[i][j], a_f[i], b_h[j]);
                    mma_f16(acc[i][j], a_f[i], b_l[j]);
                }
        }
        if (kt + 1 < nk) fillA(s ^ 1, kt + 1);
        __syncthreads();
    }

    // ---- ESIM epilogue ----
    const int g = lid >> 2, t = lid & 3;
    #pragma unroll
    for (int i = 0; i < 4; i++)
        #pragma unroll
        for (int j = 0; j < 4; j++) {
            int n = n0 + wn * 32 + j * 8 + t * 2;
            #pragma unroll
            for (int h = 0; h < 2; h++) {
                int m = m0 + wm * 64 + i * 16 + g + h * 8;
                float2 v = make_float2(acc[i][j][h*2+0], acc[i][j][h*2+1]);
                float2 av = *(const float2*)(Obase + ((size_t)z * M + m) * DIM + n);
                float* orow = Out + ((size_t)z * M + m) * OUTC + n;
                *(float2*)(orow)         = av;
                *(float2*)(orow + DIM)   = v;
                *(float2*)(orow + 2*DIM) = make_float2(av.x - v.x, av.y - v.y);
                *(float2*)(orow + 3*DIM) = make_float2(av.x * v.x, av.y * v.y);
            }
        }
}

// ---------------- fp16 split + transpose of fp32 input ----------------------
__global__ __launch_bounds__(256)
void conv_split_T(const float* __restrict__ X,
                  __half* __restrict__ Xh,  __half* __restrict__ Xl,
                  __half* __restrict__ XTh, __half* __restrict__ XTl,
                  int R, int C)
{
    __shared__ __half sh[64][65], sl[64][65];
    int z = blockIdx.z, r0 = blockIdx.y * 64, c0 = blockIdx.x * 64;
    #pragma unroll
    for (int it = 0; it < 16; it++) {
        int idx = threadIdx.x + it * 256;
        int i = idx >> 6, j = idx & 63;
        float v = X[((size_t)z * R + r0 + i) * C + c0 + j];
        __half h = __float2half_rn(v);
        __half l = __float2half_rn(v - __half2float(h));
        Xh[((size_t)z * R + r0 + i) * C + c0 + j] = h;
        Xl[((size_t)z * R + r0 + i) * C + c0 + j] = l;
        sh[i][j] = h; sl[i][j] = l;
    }
    __syncthreads();
    #pragma unroll
    for (int it = 0; it < 16; it++) {
        int idx = threadIdx.x + it * 256;
        int j = idx >> 6, i = idx & 63;
        XTh[((size_t)z * C + c0 + j) * R + r0 + i] = sh[i][j];
        XTl[((size_t)z * C + c0 + j) * R + r0 + i] = sl[i][j];
    }
}

// ---------------------------------------------------------------------------
extern "C" void kernel_launch(void* const* d_in, const int* in_sizes, int n_in,
                              void* d_out, int out_size)
{
    const float* a_bar = (const float*)d_in[0];
    const float* b_bar = (const float*)d_in[1];
    float* out = (float*)d_out;
    float* m_a = out;
    float* m_b = out + (size_t)NB * LA * OUTC;

    __half *ah, *al, *bh, *bl, *aTh, *aTl, *bTh, *bTl;
    float *pe, *prm, *pri, *pcm, *pci;
    cudaGetSymbolAddress((void**)&ah,  g_ah);   cudaGetSymbolAddress((void**)&al,  g_al);
    cudaGetSymbolAddress((void**)&bh,  g_bh);   cudaGetSymbolAddress((void**)&bl,  g_bl);
    cudaGetSymbolAddress((void**)&aTh, g_aTh);  cudaGetSymbolAddress((void**)&aTl, g_aTl);
    cudaGetSymbolAddress((void**)&bTh, g_bTh);  cudaGetSymbolAddress((void**)&bTl, g_bTl);
    cudaGetSymbolAddress((void**)&pe,  g_e);
    cudaGetSymbolAddress((void**)&prm, g_rowm); cudaGetSymbolAddress((void**)&pri, g_rowi);
    cudaGetSymbolAddress((void**)&pcm, g_colm); cudaGetSymbolAddress((void**)&pci, g_coli);

    cudaFuncSetAttribute(gemm1_k, cudaFuncAttributeMaxDynamicSharedMemorySize, G1_SMEM);
    cudaFuncSetAttribute(gemm_pv<false>, cudaFuncAttributeMaxDynamicSharedMemorySize, PV_SMEM);
    cudaFuncSetAttribute(gemm_pv<true>,  cudaFuncAttributeMaxDynamicSharedMemorySize, PV_SMEM);

    // 1) fp16 split + transposed copies of inputs
    conv_split_T<<<dim3(DIM/64, LA/64, NB), 256>>>(a_bar, ah, al, aTh, aTl, LA, DIM);
    conv_split_T<<<dim3(DIM/64, LB/64, NB), 256>>>(b_bar, bh, bl, bTh, bTl, LB, DIM);

    // 2) e = a @ b^T + on-chip row/col partial softmax stats
    gemm1_k<<<dim3(LB/128, LA/128, NB), 256, G1_SMEM>>>(ah, al, bh, bl, pe);

    // 3) reduce partials -> rowmax/rowinv, colmax/colinv
    reduce_stats_k<<<dim3(NROW/256, 2), 256>>>();

    // 4) m_a: a_tilde = softmax_row(e) @ b   (P built on the fly from e)
    gemm_pv<false><<<dim3(DIM/128, LA/128, NB), 256, PV_SMEM>>>(
        pe, prm, pri, bTh, bTl, a_bar, m_a);

    // 5) m_b: b_tilde = softmax_col(e)^T @ a (P^T built on the fly from e)
    gemm_pv<true><<<dim3(DIM/128, LB/128, NB), 256, PV_SMEM>>>(
        pe, pcm, pci, aTh, aTl, b_bar, m_b);
}